// round 1
// baseline (speedup 1.0000x reference)
#include <cuda_runtime.h>
#include <cuda_bf16.h>
#include <cstdint>

// Fuzzyfier: out[b,v,s,p] = mv >= 0.1 ? mv : 0,  mv = exp(-(x[b,v,s]-c[v,p])^2 / (2*sigma[v,p]^2))
// B=64, V=8, S=1024, P=64. fuzzy_sets layout: (V, P, 2) = (c, sigma) interleaved.
//
// Strategy: store-bandwidth-bound (128 MiB output). 16 threads per s-row, each
// thread owns 4 consecutive p-values (float4 store), iterates 4 s-rows.
// Per-(v,p) constants (c_i, k_i = -log2e/(2*sigma^2)) hoisted out of the s-loop.

#define V_DIM 8
#define S_DIM 1024
#define P_DIM 64
#define ALPHA_CUT 0.1f

__device__ __forceinline__ float ex2_approx(float t) {
    float r;
    asm("ex2.approx.ftz.f32 %0, %1;" : "=f"(r) : "f"(t));
    return r;
}

__device__ __forceinline__ float memval(float xv, float c, float k) {
    float d = xv - c;
    float t = (d * d) * k;       // k = -log2(e)/(2*sigma^2)  => 2^t = exp(-d^2/(2 s^2))
    float m = ex2_approx(t);
    return (m >= ALPHA_CUT) ? m : 0.0f;
}

__global__ __launch_bounds__(256) void fuzzyfier_kernel(
    const float* __restrict__ x,        // (B, V, S)
    const float* __restrict__ fs,       // (V, P, 2)
    float* __restrict__ out)            // (B, V, S, P)
{
    const int tid  = threadIdx.x;       // 256 threads
    const int pg   = tid & 15;          // p-group: 16 groups of 4 p-values
    const int srow = tid >> 4;          // 0..15 s-row within chunk
    const int bv   = blockIdx.y;        // 0..B*V-1
    const int v    = bv & (V_DIM - 1);
    const int s0   = blockIdx.x * 64 + srow;   // this block covers 64 s-rows

    const int p4 = pg * 4;

    // Load (c, sigma) pairs for this thread's 4 p-values; 32B-aligned float4 loads.
    const float4* fsp = reinterpret_cast<const float4*>(fs + ((size_t)v * P_DIM + p4) * 2);
    float4 f0 = fsp[0];   // c0, s0, c1, s1
    float4 f1 = fsp[1];   // c2, s2, c3, s3

    const float NHALF_LOG2E = -0.7213475204444817f;   // -log2(e)/2
    float c0 = f0.x, c1 = f0.z, c2 = f1.x, c3 = f1.z;
    float k0 = NHALF_LOG2E / (f0.y * f0.y);
    float k1 = NHALF_LOG2E / (f0.w * f0.w);
    float k2 = NHALF_LOG2E / (f1.y * f1.y);
    float k3 = NHALF_LOG2E / (f1.w * f1.w);

    const float* xrow = x + (size_t)bv * S_DIM;
    float* obase = out + (size_t)bv * S_DIM * P_DIM;

#pragma unroll
    for (int i = 0; i < 4; i++) {
        int s = s0 + i * 16;
        float xv = __ldg(xrow + s);     // 16-way broadcast within the block
        float4 r;
        r.x = memval(xv, c0, k0);
        r.y = memval(xv, c1, k1);
        r.z = memval(xv, c2, k2);
        r.w = memval(xv, c3, k3);
        reinterpret_cast<float4*>(obase + (size_t)s * P_DIM)[pg] = r;
    }
}

extern "C" void kernel_launch(void* const* d_in, const int* in_sizes, int n_in,
                              void* d_out, int out_size) {
    const float* x  = (const float*)d_in[0];        // (64, 8, 1024) f32
    const float* fs = (const float*)d_in[1];        // (8, 64, 2) f32
    float* out = (float*)d_out;                     // (64, 8, 1024, 64) f32

    // grid: x = S/64 = 16 chunks of s, y = B*V = 512
    dim3 grid(S_DIM / 64, 64 * V_DIM);
    fuzzyfier_kernel<<<grid, 256>>>(x, fs, out);
}

// round 5
// speedup vs baseline: 1.0831x; 1.0831x over previous
#include <cuda_runtime.h>
#include <cuda_bf16.h>
#include <cstdint>

// Fuzzyfier: out[b,v,s,p] = mv >= 0.1 ? mv : 0,
//            mv = exp(-(x[b,v,s]-c[v,p])^2 / (2*sigma[v,p]^2))
// B=64, V=8, S=1024, P=64. fuzzy_sets layout: (V, P, 2) interleaved (c, sigma).
//
// Math folding: with q = sqrt(log2e/2)/sigma,  u = (x - c)*q = fma(x, q, -c*q),
//   mv = 2^(-u*u)  and  mv >= 0.1  <=>  |u| <= sqrt(log2(10)) = 1.8226158...
// Per element: FFMA, FMUL (neg-src), MUFU.EX2, FSETP (parallel on u), FSEL, and
// 1/4 of an STG.128. 16 elements (4 s x 4 p) per thread, x loaded as one float4.

#define V_DIM 8
#define S_DIM 1024
#define P_DIM 64

__device__ __forceinline__ float ex2_approx(float t) {
    float r;
    asm("ex2.approx.ftz.f32 %0, %1;" : "=f"(r) : "f"(t));
    return r;
}

__device__ __forceinline__ float memval(float xv, float q, float cq) {
    float u = fmaf(xv, q, cq);          // u = (x - c) * q
    float m = ex2_approx(u * -u);       // 2^(-u^2) = exp(-d^2/(2 sigma^2))
    // alpha-cut on |u| (independent of the MUFU chain)
    return (fabsf(u) <= 1.8226158619f) ? m : 0.0f;
}

__global__ __launch_bounds__(256) void fuzzyfier_kernel(
    const float* __restrict__ x,        // (B, V, S)
    const float* __restrict__ fs,       // (V, P, 2)
    float* __restrict__ out)            // (B, V, S, P)
{
    const int tid  = threadIdx.x;       // 256 threads
    const int pg   = tid & 15;          // p-group: 16 groups of 4 p-values
    const int sq   = tid >> 4;          // 0..15: which 4-row s-slice
    const int bv   = blockIdx.y;        // 0..B*V-1
    const int v    = bv & (V_DIM - 1);
    const int s0   = blockIdx.x * 64 + sq * 4;   // block covers 64 s-rows

    const int p4 = pg * 4;

    // (c, sigma) pairs for this thread's 4 p-values: two float4 loads.
    const float4* fsp = reinterpret_cast<const float4*>(fs + ((size_t)v * P_DIM + p4) * 2);
    float4 f0 = fsp[0];   // c0, s0, c1, s1
    float4 f1 = fsp[1];   // c2, s2, c3, s3

    const float RS = 0.8493218003f;     // sqrt(log2(e)/2)
    float q0 = __fdividef(RS, f0.y), q1 = __fdividef(RS, f0.w);
    float q2 = __fdividef(RS, f1.y), q3 = __fdividef(RS, f1.w);
    float cq0 = -f0.x * q0, cq1 = -f0.z * q1;
    float cq2 = -f1.x * q2, cq3 = -f1.z * q3;

    // One vector load covers this thread's 4 consecutive s values.
    float4 xv4 = *reinterpret_cast<const float4*>(x + (size_t)bv * S_DIM + s0);
    float xs[4] = {xv4.x, xv4.y, xv4.z, xv4.w};

    float* obase = out + ((size_t)bv * S_DIM + s0) * P_DIM + p4;

#pragma unroll
    for (int i = 0; i < 4; i++) {
        float xv = xs[i];
        float4 r;
        r.x = memval(xv, q0, cq0);
        r.y = memval(xv, q1, cq1);
        r.z = memval(xv, q2, cq2);
        r.w = memval(xv, q3, cq3);
        *reinterpret_cast<float4*>(obase + (size_t)i * P_DIM) = r;
    }
}

extern "C" void kernel_launch(void* const* d_in, const int* in_sizes, int n_in,
                              void* d_out, int out_size) {
    const float* x  = (const float*)d_in[0];        // (64, 8, 1024) f32
    const float* fs = (const float*)d_in[1];        // (8, 64, 2) f32
    float* out = (float*)d_out;                     // (64, 8, 1024, 64) f32

    dim3 grid(S_DIM / 64, 64 * V_DIM);              // 16 x 512 blocks
    fuzzyfier_kernel<<<grid, 256>>>(x, fs, out);
}